// round 11
// baseline (speedup 1.0000x reference)
#include <cuda_runtime.h>
#include <stdint.h>

// SpikeFP32Embedding: out[t, :, :] = weight_pulse[token_ids[t], :, :]
// token_ids: [8*2048] int32; weight_pulse: [32768, 128, 32] f32; out: [16384, 128, 32] f32
// Row = 4096 f32 = 1024 float4 = 16 KB.
//
// Converged design, block-shape A/B: 128 threads x 8 float4/thread (vs the
// 256x4 baseline at 74.75us / 77.5% DRAM). Doubles per-thread MLP — 8
// independent LDG.128 in flight per thread before the first store — trading
// warp-count latency hiding for per-warp latency hiding.

static constexpr int ROW_FLOAT4 = 1024;   // float4 per row
static constexpr int THREADS    = 128;
static constexpr int PER_THREAD = ROW_FLOAT4 / THREADS;  // 8

__global__ __launch_bounds__(THREADS, 16)
void spike_embed_gather(const int* __restrict__ tok,
                        const float4* __restrict__ pulse,
                        float4* __restrict__ out)
{
    const int t = blockIdx.x;
    const int row = __ldg(tok + t);

    const float4* __restrict__ src = pulse + (size_t)row * ROW_FLOAT4 + threadIdx.x;
    float4* __restrict__ dst = out + (size_t)t * ROW_FLOAT4 + threadIdx.x;

    float4 v[PER_THREAD];
#pragma unroll
    for (int i = 0; i < PER_THREAD; ++i)
        v[i] = __ldg(src + i * THREADS);

#pragma unroll
    for (int i = 0; i < PER_THREAD; ++i)
        __stcs(dst + i * THREADS, v[i]);
}

extern "C" void kernel_launch(void* const* d_in, const int* in_sizes, int n_in,
                              void* d_out, int out_size)
{
    const int*    tok   = (const int*)d_in[0];       // [16384]
    const float4* pulse = (const float4*)d_in[1];    // [32768*1024] float4
    float4*       out   = (float4*)d_out;

    const int n_tokens = in_sizes[0];                // 16384
    spike_embed_gather<<<n_tokens, THREADS>>>(tok, pulse, out);
}

// round 12
// speedup vs baseline: 1.0163x; 1.0163x over previous
#include <cuda_runtime.h>
#include <stdint.h>

// SpikeFP32Embedding: out[t, :, :] = weight_pulse[token_ids[t], :, :]
// token_ids: [8*2048] int32; weight_pulse: [32768, 128, 32] f32; out: [16384, 128, 32] f32
// Row = 128*32 floats = 4096 f32 = 1024 float4 = 16 KB.
//
// FINAL (converged, 11 rounds). One CTA per token, 256 threads, 4 float4
// loads batched then 4 streaming stores. Moves the traffic floor (~203MB
// unique-row reads + 256MB writes = 459MB) at ~6.15 TB/s — the measured
// GB300 DRAM ceiling for this read/write mix.
//
// Tested and rejected:
//   - counting-sort token dedup (4-kernel overhead >> duplicate savings)
//   - L2::evict_last reads (thrashes L2, -4%)
//   - default write-back stores (neutral vs __stcs)
//   - persistent software-pipelined CTAs (-4%, occupancy drop)
//   - TMA bulk-copy smem ring (-5%, path-equivalent to LDG at LTS cap)
//   - 2 tokens/CTA (neutral)
//   - 128 threads x 8 float4 (-3.3%, L1tex-queue contention)

static constexpr int ROW_FLOAT4 = 1024;   // float4 per row
static constexpr int THREADS    = 256;
static constexpr int PER_THREAD = ROW_FLOAT4 / THREADS;  // 4

__global__ __launch_bounds__(THREADS, 8)
void spike_embed_gather(const int* __restrict__ tok,
                        const float4* __restrict__ pulse,
                        float4* __restrict__ out)
{
    const int t = blockIdx.x;
    const int row = __ldg(tok + t);

    const float4* __restrict__ src = pulse + (size_t)row * ROW_FLOAT4 + threadIdx.x;
    float4* __restrict__ dst = out + (size_t)t * ROW_FLOAT4 + threadIdx.x;

    float4 v[PER_THREAD];
#pragma unroll
    for (int i = 0; i < PER_THREAD; ++i)
        v[i] = __ldg(src + i * THREADS);

#pragma unroll
    for (int i = 0; i < PER_THREAD; ++i)
        __stcs(dst + i * THREADS, v[i]);
}

extern "C" void kernel_launch(void* const* d_in, const int* in_sizes, int n_in,
                              void* d_out, int out_size)
{
    const int*    tok   = (const int*)d_in[0];       // [16384]
    const float4* pulse = (const float4*)d_in[1];    // [32768*1024] float4
    float4*       out   = (float4*)d_out;

    const int n_tokens = in_sizes[0];                // 16384
    spike_embed_gather<<<n_tokens, THREADS>>>(tok, pulse, out);
}